// round 15
// baseline (speedup 1.0000x reference)
#include <cuda_runtime.h>
#include <stdint.h>
#include <math.h>

#define JAX_PARTITIONABLE 1

#define NROWS   65536
#define TSTEPS  12
#define WPB     16
#define THREADS 512
#define NBLOCKS 148        // 1 CTA/SM, 16 warps/SM

// output layout (float32): seq | ent | logp | cnt | lengths | mask
#define OFF_ENT  (NROWS * TSTEPS)
#define OFF_LP   (2 * NROWS * TSTEPS)
#define OFF_CNT  (3 * NROWS * TSTEPS)
#define OFF_LEN  (OFF_CNT + NROWS)
#define OFF_MASK (OFF_LEN + NROWS)

// shared layout (float slots)
#define SM_WH    0          // 128x128 = 16384
#define SM_WPT   16384      // 16 x 132 transposed Wp = 2112
#define SM_B     18496      // 128
#define SM_BP    18624      // 16
#define SM_H0    18640      // 128
#define SM_KEY   18768      // 24 u32
#define SM_HS    18792      // 16 warps * 6 pairs * 128 f32x2 = 24576 floats
#define SM_SEQ   43368      // 16 warps * 12 * 12 int = 2304
#define SM_ST    45672      // 16 warps * 12 * 8  int = 1536
#define SM_TOTF  47208      // 188832 bytes (< 227KB single-CTA limit)

typedef unsigned long long u64t;

// Precomputed x@Wx + b combo table: index (p0+1)*17 + (p1+1), 128 floats each.
__device__ float g_xwc[289 * 128];

__device__ __forceinline__ u64t pk2(float lo, float hi) {
    u64t r;
    asm("mov.b64 %0, {%1, %2};" : "=l"(r) : "f"(lo), "f"(hi));
    return r;
}
__device__ __forceinline__ u64t pkdup(float v) { return pk2(v, v); }
__device__ __forceinline__ void upk2(u64t x, float& lo, float& hi) {
    asm("mov.b64 {%0, %1}, %2;" : "=f"(lo), "=f"(hi) : "l"(x));
}
__device__ __forceinline__ u64t fma2(u64t a, u64t b, u64t c) {
    u64t d;
    asm("fma.rn.f32x2 %0, %1, %2, %3;" : "=l"(d) : "l"(a), "l"(b), "l"(c));
    return d;
}
__device__ __forceinline__ u64t add2(u64t a, u64t b) {
    u64t d;
    asm("add.rn.f32x2 %0, %1, %2;" : "=l"(d) : "l"(a), "l"(b));
    return d;
}

__device__ __forceinline__ uint32_t rotl32(uint32_t x, int n) {
    return (x << n) | (x >> (32 - n));
}

// Threefry-2x32, 20 rounds (exact JAX cipher)
__device__ __forceinline__ void tf2x32(uint32_t k0, uint32_t k1,
                                       uint32_t &x0, uint32_t &x1) {
    uint32_t k2 = k0 ^ k1 ^ 0x1BD11BDAu;
    x0 += k0; x1 += k1;
#define TFR(r) { x0 += x1; x1 = rotl32(x1, (r)); x1 ^= x0; }
    TFR(13) TFR(15) TFR(26) TFR(6)
    x0 += k1; x1 += k2 + 1u;
    TFR(17) TFR(29) TFR(16) TFR(24)
    x0 += k2; x1 += k0 + 2u;
    TFR(13) TFR(15) TFR(26) TFR(6)
    x0 += k0; x1 += k1 + 3u;
    TFR(17) TFR(29) TFR(16) TFR(24)
    x0 += k1; x1 += k2 + 4u;
    TFR(13) TFR(15) TFR(26) TFR(6)
    x0 += k2; x1 += k0 + 5u;
#undef TFR
}

__device__ __forceinline__ uint32_t gbits(uint32_t k0, uint32_t k1, uint32_t idx) {
#if JAX_PARTITIONABLE
    uint32_t a = 0u, b = idx;
    tf2x32(k0, k1, a, b);
    return a ^ b;
#else
    const uint32_t half = (uint32_t)(NROWS * 16) / 2u;
    if (idx < half) {
        uint32_t a = idx, b = idx + half;
        tf2x32(k0, k1, a, b);
        return a;
    } else {
        uint32_t a = idx - half, b = idx;
        tf2x32(k0, k1, a, b);
        return b;
    }
#endif
}

// Prologue: build the (p0,p1) -> xw+b combo table. 289 blocks x 128 threads.
__global__ void build_xwc(const float* __restrict__ Wx, const float* __restrict__ b) {
    int c = blockIdx.x;
    int k = threadIdx.x;
    int i = c / 17, j = c % 17;
    float v = b[k];
    if (i > 0) v += Wx[(i - 1) * 128 + k];
    if (j > 0) v += Wx[(16 + (j - 1)) * 128 + k];
    g_xwc[c * 128 + k] = v;
}

// One group of R rows (R multiple of 4). h pair-interleaved in smem:
// hw[pair*128 + k] = (h_{2p}[k], h_{2p+1}[k]) packed f32x2.
template <int R>
__device__ __forceinline__ void run_group(
    int rowBase, float* __restrict__ sm, u64t* __restrict__ hw,
    int* __restrict__ seqw, int* __restrict__ stw,
    const float4* __restrict__ xwc4, float* __restrict__ out,
    int lane, int g, int tk,
    const u64t* __restrict__ ivd,
    u64t hi0, u64t hi1, u64t hi2, u64t hi3, float bpt)
{
    constexpr int NP = R / 2;          // row pairs
    constexpr int PH = R / 4;          // pairs per half-warp (logits)
    constexpr int SS = R / 2;          // sampler streams per half
    constexpr int NA = (NP + 1) / 2;   // xw pairs prefetched before matvec
    const float NEG_INF = __int_as_float(0xff800000);
    const uint32_t* keys = (const uint32_t*)(sm + SM_KEY);

    // ---- init group ----
#pragma unroll
    for (int p = 0; p < NP; p++) {
        u64t* pw = hw + p * 128 + lane * 4;
        pw[0] = hi0; pw[1] = hi1; pw[2] = hi2; pw[3] = hi3;
    }
    if (lane < R) {
        int* st = stw + lane * 8;
        st[0] = 1; st[1] = 0; st[2] = 1; st[3] = 0; st[4] = 1; st[5] = -1; st[6] = -1;
        out[OFF_MASK + (size_t)(rowBase + lane) * 13] = 1.0f;
    }
    __syncwarp();

    for (int t = 0; t < TSTEPS; t++) {
        const uint32_t k0 = keys[2 * t];
        const uint32_t k1 = keys[2 * t + 1];

        // ---- prefetch xw+b for the FIRST NA pairs (held across matvec) ----
        float4 xa[NA], xb[NA];
        if (t > 0) {
#pragma unroll
            for (int p = 0; p < NA; p++) {
                int ia = (stw[(2 * p) * 8 + 5] + 1) * 17 + (stw[(2 * p) * 8 + 6] + 1);
                int ib = (stw[(2 * p + 1) * 8 + 5] + 1) * 17 + (stw[(2 * p + 1) * 8 + 6] + 1);
                xa[p] = __ldg(xwc4 + ia * 32 + lane);
                xb[p] = __ldg(xwc4 + ib * 32 + lane);
            }
        }

        // ---- h @ Wh with packed FFMA2 (Wh in smem; half-staged hk) ----
        u64t acc2[NP][4];
#pragma unroll
        for (int p = 0; p < NP; p++) {
            acc2[p][0] = 0ull; acc2[p][1] = 0ull; acc2[p][2] = 0ull; acc2[p][3] = 0ull;
        }
        {
            const float4* Wh4 = (const float4*)sm;  // SM_WH == 0
#pragma unroll 1
            for (int k4 = 0; k4 < 32; k4++) {
                // first half: k = 4k4, 4k4+1
                u64t hA0[NP], hA1[NP];
#pragma unroll
                for (int p = 0; p < NP; p++) {
                    ulonglong2 hA = *(const ulonglong2*)(hw + p * 128 + 4 * k4);
                    hA0[p] = hA.x; hA1[p] = hA.y;
                }
#pragma unroll
                for (int kk = 0; kk < 2; kk++) {
                    float4 w = Wh4[(k4 * 4 + kk) * 32 + lane];
                    u64t wd0 = pkdup(w.x), wd1 = pkdup(w.y);
                    u64t wd2 = pkdup(w.z), wd3 = pkdup(w.w);
#pragma unroll
                    for (int p = 0; p < NP; p++) {
                        u64t hv = kk ? hA1[p] : hA0[p];
                        acc2[p][0] = fma2(hv, wd0, acc2[p][0]);
                        acc2[p][1] = fma2(hv, wd1, acc2[p][1]);
                        acc2[p][2] = fma2(hv, wd2, acc2[p][2]);
                        acc2[p][3] = fma2(hv, wd3, acc2[p][3]);
                    }
                }
                // second half: k = 4k4+2, 4k4+3
                u64t hB0[NP], hB1[NP];
#pragma unroll
                for (int p = 0; p < NP; p++) {
                    ulonglong2 hB = *(const ulonglong2*)(hw + p * 128 + 4 * k4 + 2);
                    hB0[p] = hB.x; hB1[p] = hB.y;
                }
#pragma unroll
                for (int kk = 0; kk < 2; kk++) {
                    float4 w = Wh4[(k4 * 4 + 2 + kk) * 32 + lane];
                    u64t wd0 = pkdup(w.x), wd1 = pkdup(w.y);
                    u64t wd2 = pkdup(w.z), wd3 = pkdup(w.w);
#pragma unroll
                    for (int p = 0; p < NP; p++) {
                        u64t hv = kk ? hB1[p] : hB0[p];
                        acc2[p][0] = fma2(hv, wd0, acc2[p][0]);
                        acc2[p][1] = fma2(hv, wd1, acc2[p][1]);
                        acc2[p][2] = fma2(hv, wd2, acc2[p][2]);
                        acc2[p][3] = fma2(hv, wd3, acc2[p][3]);
                    }
                }
            }
            __syncwarp();

            // ---- late xw loads for remaining pairs ----
            float4 xa2[NP - NA + 1], xb2[NP - NA + 1];
            if (t > 0) {
#pragma unroll
                for (int p = NA; p < NP; p++) {
                    int ia = (stw[(2 * p) * 8 + 5] + 1) * 17 + (stw[(2 * p) * 8 + 6] + 1);
                    int ib = (stw[(2 * p + 1) * 8 + 5] + 1) * 17 + (stw[(2 * p + 1) * 8 + 6] + 1);
                    xa2[p - NA] = __ldg(xwc4 + ia * 32 + lane);
                    xb2[p - NA] = __ldg(xwc4 + ib * 32 + lane);
                }
            }

            // h_new = tanh(acc + (xw + b)) ; store back pair-interleaved
#pragma unroll
            for (int p = 0; p < NP; p++) {
                u64t xw0, xw1, xw2, xw3;
                if (t == 0) {
                    xw0 = ivd[0]; xw1 = ivd[1]; xw2 = ivd[2]; xw3 = ivd[3];
                } else {
                    float4 va = (p < NA) ? xa[p] : xa2[p - NA];
                    float4 vb = (p < NA) ? xb[p] : xb2[p - NA];
                    xw0 = pk2(va.x, vb.x);
                    xw1 = pk2(va.y, vb.y);
                    xw2 = pk2(va.z, vb.z);
                    xw3 = pk2(va.w, vb.w);
                }
                u64t s0 = add2(acc2[p][0], xw0);
                u64t s1 = add2(acc2[p][1], xw1);
                u64t s2 = add2(acc2[p][2], xw2);
                u64t s3 = add2(acc2[p][3], xw3);
                u64t* pw = hw + p * 128 + lane * 4;
                float lo, hi;
                upk2(s0, lo, hi); pw[0] = pk2(tanhf(lo), tanhf(hi));
                upk2(s1, lo, hi); pw[1] = pk2(tanhf(lo), tanhf(hi));
                upk2(s2, lo, hi); pw[2] = pk2(tanhf(lo), tanhf(hi));
                upk2(s3, lo, hi); pw[3] = pk2(tanhf(lo), tanhf(hi));
            }
            __syncwarp();
        }

        // ---- logits: lane = token tk; PH pairs for this half ----
        float lg[SS];
        {
            u64t accl2[PH];
#pragma unroll
            for (int q = 0; q < PH; q++) accl2[q] = 0ull;
            const float4* WpT4 = (const float4*)(sm + SM_WPT);
#pragma unroll 4
            for (int k4 = 0; k4 < 32; k4++) {
                float4 wp = WpT4[tk * 33 + k4];
                u64t wd0 = pkdup(wp.x), wd1 = pkdup(wp.y);
                u64t wd2 = pkdup(wp.z), wd3 = pkdup(wp.w);
#pragma unroll
                for (int q = 0; q < PH; q++) {
                    const u64t* ph = hw + (g + 2 * q) * 128 + 4 * k4;
                    ulonglong2 hA = *(const ulonglong2*)(ph);
                    ulonglong2 hB = *(const ulonglong2*)(ph + 2);
                    accl2[q] = fma2(hA.x, wd0, accl2[q]);
                    accl2[q] = fma2(hA.y, wd1, accl2[q]);
                    accl2[q] = fma2(hB.x, wd2, accl2[q]);
                    accl2[q] = fma2(hB.y, wd3, accl2[q]);
                }
            }
#pragma unroll
            for (int q = 0; q < PH; q++) {
                float lo, hi;
                upk2(accl2[q], lo, hi);
                lg[2 * q]     = lo + bpt;
                lg[2 * q + 1] = hi + bpt;
            }
        }

        // stream s -> row r = 2*(g + 2*(s>>1)) + (s&1)
        int rmap[SS];
#pragma unroll
        for (int s = 0; s < SS; s++) rmap[s] = 2 * (g + 2 * (s >> 1)) + (s & 1);

        // ---- constraints (PRE-update state) ----
        bool ok[SS];
#pragma unroll
        for (int s = 0; s < SS; s++) {
            int r = rmap[s];
            int cnt = stw[r * 8 + 0], ln = stw[r * 8 + 1], hv = stw[r * 8 + 3];
            int cl = cnt + ln;
            bool o = true;
            if (tk >= 8 && cl < 2) o = false;
            if (tk <  8 && cl > TSTEPS - 2) o = false;
            if (tk == 8 && cnt == 1 && hv == 0) o = false;
            ok[s] = o;
        }

        // ---- stage 1: max over 16 tokens ----
        float mx[SS];
#pragma unroll
        for (int s = 0; s < SS; s++) mx[s] = lg[s];
#pragma unroll
        for (int d = 1; d < 16; d <<= 1)
#pragma unroll
            for (int s = 0; s < SS; s++)
                mx[s] = fmaxf(mx[s], __shfl_xor_sync(0xffffffffu, mx[s], d));

        // ---- per-lane: ex, masked sums, gumbel score (argmax is lzm-invariant) ----
        float a_[SS], ex[SS], zm[SS], Sw[SS], bsc[SS];
        int bi[SS];
#pragma unroll
        for (int s = 0; s < SS; s++) {
            a_[s] = lg[s] - mx[s];
            ex[s] = expf(a_[s]);
            bool pos = ok[s] && (ex[s] > 0.0f);
            zm[s] = ok[s] ? ex[s] : 0.0f;
            Sw[s] = ok[s] ? ex[s] * a_[s] : 0.0f;
            uint32_t idx = ((uint32_t)(rowBase + rmap[s])) * 16u + (uint32_t)tk;
            uint32_t bts = gbits(k0, k1, idx);
            float f = __uint_as_float((bts >> 9) | 0x3f800000u) - 1.0f;
            float u = (f == 0.0f) ? 1.17549435e-38f : f;
            float gu = -logf(-logf(u));
            bsc[s] = pos ? (a_[s] + gu) : NEG_INF;
            bi[s]  = tk;
        }

        // ---- stage 2 (fused): zm + S sums AND argmax, same 4 rounds ----
#pragma unroll
        for (int d = 1; d < 16; d <<= 1) {
#pragma unroll
            for (int s = 0; s < SS; s++) {
                zm[s] += __shfl_xor_sync(0xffffffffu, zm[s], d);
                Sw[s] += __shfl_xor_sync(0xffffffffu, Sw[s], d);
                float os = __shfl_xor_sync(0xffffffffu, bsc[s], d);
                int   oi = __shfl_xor_sync(0xffffffffu, bi[s], d);
                if (os > bsc[s] || (os == bsc[s] && oi < bi[s])) { bsc[s] = os; bi[s] = oi; }
            }
        }

        // ---- finalize: ent = lzm - S/zm ; lp = a_win - lzm ----
        float ent[SS], lp[SS];
#pragma unroll
        for (int s = 0; s < SS; s++) {
            float lzm = logf(zm[s]);
            ent[s] = lzm - Sw[s] / zm[s];
            float a_win = __shfl_sync(0xffffffffu, a_[s], (lane & 16) + bi[s]);
            lp[s] = a_win - lzm;
        }

        // ---- writer lanes: token/state/outputs ----
        if (tk == 0) {
#pragma unroll
            for (int s = 0; s < SS; s++) {
                int r   = rmap[s];
                int tok = bi[s];
                int* st = stw + r * 8;
                int row = rowBase + r;

                seqw[r * 12 + t] = tok;
                int ar  = (tok < 4) ? 2 : ((tok < 8) ? 1 : 0);
                int cnt = st[0] - 1 + ar;
                int ln  = st[1] + 1;
                int act = (cnt > 0) && st[2];
                st[0] = cnt; st[1] = ln; st[2] = act;
                st[3] = st[3] | (tok >= 9);
                st[4] += act;

                out[(size_t)row * 12 + t]                = (float)tok;
                out[OFF_ENT + (size_t)row * 12 + t]      = ent[s];
                out[OFF_LP  + (size_t)row * 12 + t]      = lp[s];
                out[OFF_MASK + (size_t)row * 13 + 1 + t] = act ? 1.0f : 0.0f;
            }
        }
        __syncwarp();

        // ---- parent/sibling scan, parallel across lanes 0..R-1 ----
        if (lane < R) {
            int r = lane;
            int tok = seqw[r * 12 + t];
            int ps0, ps1;
            if (tok < 8) {
                ps0 = tok; ps1 = -1;
            } else {
                ps0 = -1; ps1 = -1;
                int c = 0;
                bool found = false;
                for (int i = t; i >= 0; i--) {
                    int tk2 = seqw[r * 12 + i];
                    int a2 = (tk2 < 4) ? 2 : ((tk2 < 8) ? 1 : 0);
                    c += a2 - 1;
                    if (!found && c == 0) {
                        ps0 = tk2;
                        ps1 = (i + 1 < TSTEPS) ? seqw[r * 12 + i + 1] : -1;
                        found = true;
                    }
                }
            }
            stw[r * 8 + 5] = ps0;
            stw[r * 8 + 6] = ps1;
        }
        __syncwarp();
    }

    // ---- finalize group ----
    if (lane < R) {
        out[OFF_CNT + rowBase + lane] = (float)stw[lane * 8 + 0];
        out[OFF_LEN + rowBase + lane] = (float)stw[lane * 8 + 4];
    }
    __syncwarp();
}

__global__ void __launch_bounds__(THREADS, 1)
eq_sampler(const float* __restrict__ in0, const float* __restrict__ h0,
           const float* __restrict__ Wx, const float* __restrict__ Wh,
           const float* __restrict__ b,  const float* __restrict__ Wp,
           const float* __restrict__ bp, float* __restrict__ out) {
    extern __shared__ float sm[];
    int* smi = (int*)sm;
    const int tid = threadIdx.x;

    for (int i = tid; i < 16384; i += THREADS) sm[SM_WH + i] = Wh[i];
    // transposed, padded Wp: WpT[tok][k], stride 132
    for (int i = tid; i < 2048; i += THREADS) {
        int tok = i >> 7, k = i & 127;
        sm[SM_WPT + tok * 132 + k] = Wp[k * 16 + tok];
    }
    if (tid < 128) sm[SM_B  + tid] = b[tid];
    if (tid < 16)  sm[SM_BP + tid] = bp[tid];
    if (tid < 128) sm[SM_H0 + tid] = h0[tid];

    if (tid == 0) {
        uint32_t* kp = (uint32_t*)(sm + SM_KEY);
#if JAX_PARTITIONABLE
        for (int t = 0; t < TSTEPS; t++) {
            uint32_t a = 0u, bb = (uint32_t)t;
            tf2x32(0u, 42u, a, bb);
            kp[2 * t] = a; kp[2 * t + 1] = bb;
        }
#else
        uint32_t ov[24];
        for (int j = 0; j < 12; j++) {
            uint32_t a = (uint32_t)j, bb = (uint32_t)(j + 12);
            tf2x32(0u, 42u, a, bb);
            ov[j] = a; ov[12 + j] = bb;
        }
        for (int t = 0; t < TSTEPS; t++) { kp[2 * t] = ov[2 * t]; kp[2 * t + 1] = ov[2 * t + 1]; }
#endif
    }
    __syncthreads();

    const int wid  = tid >> 5;
    const int lane = tid & 31;
    const int g    = lane >> 4;
    const int tk   = lane & 15;

    u64t* hw  = (u64t*)(sm + SM_HS) + wid * 768;        // 6 pairs x 128 packed f32x2
    int* seqw = smi + SM_SEQ + wid * 144;               // 12 rows x 12
    int* stw  = smi + SM_ST  + wid * 96;                // 12 rows x 8

    // t=0 input projection (identical for all rows) from global
    float4 xw0v;
    {
        float s0 = 0.f, s1 = 0.f, s2 = 0.f, s3 = 0.f;
#pragma unroll
        for (int k = 0; k < 32; k++) {
            float iv = __ldg(in0 + k);
            const float* wr = Wx + k * 128 + lane * 4;
            s0 = fmaf(iv, __ldg(wr + 0), s0);
            s1 = fmaf(iv, __ldg(wr + 1), s1);
            s2 = fmaf(iv, __ldg(wr + 2), s2);
            s3 = fmaf(iv, __ldg(wr + 3), s3);
        }
        xw0v = make_float4(s0, s1, s2, s3);
    }
    const float4 bvecv = ((const float4*)(sm + SM_B))[lane];
    const float4 hinit = ((const float4*)(sm + SM_H0))[lane];
    const float  bpt   = sm[SM_BP + tk];
    const float4* xwc4 = (const float4*)g_xwc;

    u64t ivd[4];
    ivd[0] = pkdup(xw0v.x + bvecv.x);
    ivd[1] = pkdup(xw0v.y + bvecv.y);
    ivd[2] = pkdup(xw0v.z + bvecv.z);
    ivd[3] = pkdup(xw0v.w + bvecv.w);
    const u64t hi0 = pkdup(hinit.x), hi1 = pkdup(hinit.y);
    const u64t hi2 = pkdup(hinit.z), hi3 = pkdup(hinit.w);

    const int totalWarps = gridDim.x * WPB;              // 2368
    const int gwid = blockIdx.x * WPB + wid;

    // main: 4736 R=12 groups -> exactly 2 per warp (rows 0..56831)
    for (int grp = gwid; grp < 4736; grp += totalWarps)
        run_group<12>(grp * 12, sm, hw, seqw, stw, xwc4, out,
                      lane, g, tk, ivd, hi0, hi1, hi2, hi3, bpt);

    // tail: 2176 R=4 groups, <=1 per warp (rows 56832..65535)
    for (int grp = gwid; grp < 2176; grp += totalWarps)
        run_group<4>(56832 + grp * 4, sm, hw, seqw, stw, xwc4, out,
                     lane, g, tk, ivd, hi0, hi1, hi2, hi3, bpt);
}

extern "C" void kernel_launch(void* const* d_in, const int* in_sizes, int n_in,
                              void* d_out, int out_size) {
    int base = (in_sizes[0] == 1) ? 1 : 0;
    const float* in0 = (const float*)d_in[base + 0];
    const float* h0  = (const float*)d_in[base + 1];
    const float* Wx  = (const float*)d_in[base + 2];
    const float* Wh  = (const float*)d_in[base + 3];
    const float* b   = (const float*)d_in[base + 4];
    const float* Wp  = (const float*)d_in[base + 5];
    const float* bp  = (const float*)d_in[base + 6];

    build_xwc<<<289, 128>>>(Wx, b);

    size_t smem = (size_t)SM_TOTF * sizeof(float);
    cudaFuncSetAttribute(eq_sampler, cudaFuncAttributeMaxDynamicSharedMemorySize, (int)smem);
    eq_sampler<<<NBLOCKS, THREADS, smem>>>(in0, h0, Wx, Wh, b, Wp, bp, (float*)d_out);
}

// round 16
// speedup vs baseline: 1.0785x; 1.0785x over previous
#include <cuda_runtime.h>
#include <stdint.h>
#include <math.h>

#define JAX_PARTITIONABLE 1

#define NROWS   65536
#define TSTEPS  12
#define WPB     8
#define THREADS 256
#define NBLOCKS 296        // 2 CTAs/SM on 148 SMs

// output layout (float32): seq | ent | logp | cnt | lengths | mask
#define OFF_ENT  (NROWS * TSTEPS)
#define OFF_LP   (2 * NROWS * TSTEPS)
#define OFF_CNT  (3 * NROWS * TSTEPS)
#define OFF_LEN  (OFF_CNT + NROWS)
#define OFF_MASK (OFF_LEN + NROWS)

// shared layout (float slots)
#define SM_WH    0          // 128x128 = 16384
#define SM_WPT   16384      // 16 x 132 (transposed Wp, padded) = 2112
#define SM_B     18496      // 128
#define SM_BP    18624      // 16
#define SM_H0    18640      // 128
#define SM_KEY   18768      // 24 u32
#define SM_HS    18792      // 8 warps * 4 pairs * 128 f32x2 = 8192 floats (16B aligned)
#define SM_SEQ   26984      // 8 warps * 8 * 12 int = 768
#define SM_ST    27752      // 8 warps * 8 * 8  int = 512
#define SM_TOTF  28264      // 113056 bytes -> 2 CTAs/SM fit

typedef unsigned long long u64t;

// Precomputed x@Wx + b combo table: index (p0+1)*17 + (p1+1), 128 floats each.
__device__ float g_xwc[289 * 128];

__device__ __forceinline__ u64t pk2(float lo, float hi) {
    u64t r;
    asm("mov.b64 %0, {%1, %2};" : "=l"(r) : "f"(lo), "f"(hi));
    return r;
}
__device__ __forceinline__ u64t pkdup(float v) { return pk2(v, v); }
__device__ __forceinline__ void upk2(u64t x, float& lo, float& hi) {
    asm("mov.b64 {%0, %1}, %2;" : "=f"(lo), "=f"(hi) : "l"(x));
}
// packed dual-fp32 FMA (Blackwell): lo/hi halves are independent fp32 FMAs
__device__ __forceinline__ u64t fma2(u64t a, u64t b, u64t c) {
    u64t d;
    asm("fma.rn.f32x2 %0, %1, %2, %3;" : "=l"(d) : "l"(a), "l"(b), "l"(c));
    return d;
}
__device__ __forceinline__ u64t add2(u64t a, u64t b) {
    u64t d;
    asm("add.rn.f32x2 %0, %1, %2;" : "=l"(d) : "l"(a), "l"(b));
    return d;
}

__device__ __forceinline__ uint32_t rotl32(uint32_t x, int n) {
    return (x << n) | (x >> (32 - n));
}

// Threefry-2x32, 20 rounds (exact JAX cipher)
__device__ __forceinline__ void tf2x32(uint32_t k0, uint32_t k1,
                                       uint32_t &x0, uint32_t &x1) {
    uint32_t k2 = k0 ^ k1 ^ 0x1BD11BDAu;
    x0 += k0; x1 += k1;
#define TFR(r) { x0 += x1; x1 = rotl32(x1, (r)); x1 ^= x0; }
    TFR(13) TFR(15) TFR(26) TFR(6)
    x0 += k1; x1 += k2 + 1u;
    TFR(17) TFR(29) TFR(16) TFR(24)
    x0 += k2; x1 += k0 + 2u;
    TFR(13) TFR(15) TFR(26) TFR(6)
    x0 += k0; x1 += k1 + 3u;
    TFR(17) TFR(29) TFR(16) TFR(24)
    x0 += k1; x1 += k2 + 4u;
    TFR(13) TFR(15) TFR(26) TFR(6)
    x0 += k2; x1 += k0 + 5u;
#undef TFR
}

__device__ __forceinline__ uint32_t gbits(uint32_t k0, uint32_t k1, uint32_t idx) {
#if JAX_PARTITIONABLE
    uint32_t a = 0u, b = idx;
    tf2x32(k0, k1, a, b);
    return a ^ b;
#else
    const uint32_t half = (uint32_t)(NROWS * 16) / 2u;
    if (idx < half) {
        uint32_t a = idx, b = idx + half;
        tf2x32(k0, k1, a, b);
        return a;
    } else {
        uint32_t a = idx - half, b = idx;
        tf2x32(k0, k1, a, b);
        return b;
    }
#endif
}

// Prologue: build the (p0,p1) -> xw+b combo table. 289 blocks x 128 threads.
__global__ void build_xwc(const float* __restrict__ Wx, const float* __restrict__ b) {
    int c = blockIdx.x;
    int k = threadIdx.x;
    int i = c / 17, j = c % 17;
    float v = b[k];
    if (i > 0) v += Wx[(i - 1) * 128 + k];
    if (j > 0) v += Wx[(16 + (j - 1)) * 128 + k];
    g_xwc[c * 128 + k] = v;
}

// One group of R rows (R even, R/2 row-pairs). h stored pair-interleaved:
// hw[pair*128 + k] = (h_{2*pair}[k], h_{2*pair+1}[k]) as packed f32x2.
template <int R>
__device__ __forceinline__ void run_group(
    int rowBase, float* __restrict__ sm, u64t* __restrict__ hw,
    int* __restrict__ seqw, int* __restrict__ stw,
    const float4* __restrict__ xwc4, float* __restrict__ out,
    int lane, int g, int tk,
    const u64t* __restrict__ ivd,    // 4: dup(xw0+b) per col (t==0)
    u64t hinit0, u64t hinit1, u64t hinit2, u64t hinit3,
    float bpt)
{
    constexpr int NP = R / 2;     // row pairs
    constexpr int PH = R / 4;     // pairs per half-warp
    constexpr int SS = R / 2;     // scalar sampler streams per half
    const float NEG_INF = __int_as_float(0xff800000);
    const uint32_t* keys = (const uint32_t*)(sm + SM_KEY);

    // stream s -> row r = 2*(g + 2*(s>>1)) + (s&1)  (loop-invariant)
    int rmap[SS];
#pragma unroll
    for (int s = 0; s < SS; s++) rmap[s] = 2 * (g + 2 * (s >> 1)) + (s & 1);

    // ---- init group ----
#pragma unroll
    for (int p = 0; p < NP; p++) {
        u64t* pw = hw + p * 128 + lane * 4;
        pw[0] = hinit0; pw[1] = hinit1; pw[2] = hinit2; pw[3] = hinit3;
    }
    if (lane < R) {
        int* st = stw + lane * 8;
        st[0] = 1; st[1] = 0; st[2] = 1; st[3] = 0; st[4] = 1; st[5] = -1; st[6] = -1;
        out[OFF_MASK + (size_t)(rowBase + lane) * 13] = 1.0f;
    }
    __syncwarp();

    for (int t = 0; t < TSTEPS; t++) {
        const uint32_t k0 = keys[2 * t];
        const uint32_t k1 = keys[2 * t + 1];

        // ---- prefetch xw+b rows (combo table) for this step; consume AFTER matvec ----
        float4 xa[NP], xb[NP];
        if (t > 0) {
#pragma unroll
            for (int p = 0; p < NP; p++) {
                int ia = (stw[(2 * p) * 8 + 5] + 1) * 17 + (stw[(2 * p) * 8 + 6] + 1);
                int ib = (stw[(2 * p + 1) * 8 + 5] + 1) * 17 + (stw[(2 * p + 1) * 8 + 6] + 1);
                xa[p] = __ldg(xwc4 + ia * 32 + lane);
                xb[p] = __ldg(xwc4 + ib * 32 + lane);
            }
        }

        // ---- h @ Wh with packed FFMA2 (acc starts at 0; xw+b added late) ----
        u64t acc2[NP][4];
#pragma unroll
        for (int p = 0; p < NP; p++) {
            acc2[p][0] = 0ull; acc2[p][1] = 0ull; acc2[p][2] = 0ull; acc2[p][3] = 0ull;
        }
        {
            const float4* Wh4 = (const float4*)sm;  // SM_WH == 0
#pragma unroll 1
            for (int k4 = 0; k4 < 32; k4++) {
                u64t hk[NP][4];
#pragma unroll
                for (int p = 0; p < NP; p++) {
                    const u64t* ph = hw + p * 128 + 4 * k4;
                    hk[p][0] = ph[0]; hk[p][1] = ph[1];
                    hk[p][2] = ph[2]; hk[p][3] = ph[3];
                }
#pragma unroll
                for (int kk = 0; kk < 4; kk++) {
                    float4 w = Wh4[(k4 * 4 + kk) * 32 + lane];
                    u64t wd0 = pkdup(w.x), wd1 = pkdup(w.y);
                    u64t wd2 = pkdup(w.z), wd3 = pkdup(w.w);
#pragma unroll
                    for (int p = 0; p < NP; p++) {
                        acc2[p][0] = fma2(hk[p][kk], wd0, acc2[p][0]);
                        acc2[p][1] = fma2(hk[p][kk], wd1, acc2[p][1]);
                        acc2[p][2] = fma2(hk[p][kk], wd2, acc2[p][2]);
                        acc2[p][3] = fma2(hk[p][kk], wd3, acc2[p][3]);
                    }
                }
            }
            __syncwarp();
            // h_new = tanh(acc + (xw + b)) ; store back pair-interleaved
#pragma unroll
            for (int p = 0; p < NP; p++) {
                u64t xw0, xw1, xw2, xw3;
                if (t == 0) {
                    xw0 = ivd[0]; xw1 = ivd[1]; xw2 = ivd[2]; xw3 = ivd[3];
                } else {
                    xw0 = pk2(xa[p].x, xb[p].x);
                    xw1 = pk2(xa[p].y, xb[p].y);
                    xw2 = pk2(xa[p].z, xb[p].z);
                    xw3 = pk2(xa[p].w, xb[p].w);
                }
                u64t s0 = add2(acc2[p][0], xw0);
                u64t s1 = add2(acc2[p][1], xw1);
                u64t s2 = add2(acc2[p][2], xw2);
                u64t s3 = add2(acc2[p][3], xw3);
                u64t* pw = hw + p * 128 + lane * 4;
                float lo, hi;
                upk2(s0, lo, hi); pw[0] = pk2(tanhf(lo), tanhf(hi));
                upk2(s1, lo, hi); pw[1] = pk2(tanhf(lo), tanhf(hi));
                upk2(s2, lo, hi); pw[2] = pk2(tanhf(lo), tanhf(hi));
                upk2(s3, lo, hi); pw[3] = pk2(tanhf(lo), tanhf(hi));
            }
            __syncwarp();
        }

        // ---- logits: lane = token tk; PH pairs for this half ----
        float lg[SS];
        {
            u64t accl2[PH];
#pragma unroll
            for (int q = 0; q < PH; q++) accl2[q] = 0ull;
            const float4* WpT4 = (const float4*)(sm + SM_WPT);
#pragma unroll 4
            for (int k4 = 0; k4 < 32; k4++) {
                float4 wp = WpT4[tk * 33 + k4];
                u64t wd0 = pkdup(wp.x), wd1 = pkdup(wp.y);
                u64t wd2 = pkdup(wp.z), wd3 = pkdup(wp.w);
#pragma unroll
                for (int q = 0; q < PH; q++) {
                    const u64t* ph = hw + (g + 2 * q) * 128 + 4 * k4;
                    ulonglong2 hA = *(const ulonglong2*)(ph);
                    ulonglong2 hB = *(const ulonglong2*)(ph + 2);
                    accl2[q] = fma2(hA.x, wd0, accl2[q]);
                    accl2[q] = fma2(hA.y, wd1, accl2[q]);
                    accl2[q] = fma2(hB.x, wd2, accl2[q]);
                    accl2[q] = fma2(hB.y, wd3, accl2[q]);
                }
            }
#pragma unroll
            for (int q = 0; q < PH; q++) {
                float lo, hi;
                upk2(accl2[q], lo, hi);
                lg[2 * q]     = lo + bpt;
                lg[2 * q + 1] = hi + bpt;
            }
        }

        // ---- constraints (PRE-update state) ----
        bool ok[SS];
#pragma unroll
        for (int s = 0; s < SS; s++) {
            int r = rmap[s];
            int cnt = stw[r * 8 + 0], ln = stw[r * 8 + 1], hv = stw[r * 8 + 3];
            int cl = cnt + ln;
            bool o = true;
            if (tk >= 8 && cl < 2) o = false;
            if (tk <  8 && cl > TSTEPS - 2) o = false;
            if (tk == 8 && cnt == 1 && hv == 0) o = false;
            ok[s] = o;
        }

        // ---- stage 1: max over 16 tokens ----
        float mx[SS];
#pragma unroll
        for (int s = 0; s < SS; s++) mx[s] = lg[s];
#pragma unroll
        for (int d = 1; d < 16; d <<= 1)
#pragma unroll
            for (int s = 0; s < SS; s++)
                mx[s] = fmaxf(mx[s], __shfl_xor_sync(0xffffffffu, mx[s], d));

        // ---- per-lane: ex, masked sums, gumbel score (argmax is lzm-invariant) ----
        float a_[SS], ex[SS], zm[SS], Sw[SS], bsc[SS];
        int bi[SS];
#pragma unroll
        for (int s = 0; s < SS; s++) {
            a_[s] = lg[s] - mx[s];
            ex[s] = expf(a_[s]);
            bool pos = ok[s] && (ex[s] > 0.0f);
            zm[s] = ok[s] ? ex[s] : 0.0f;
            Sw[s] = ok[s] ? ex[s] * a_[s] : 0.0f;
            uint32_t idx = ((uint32_t)(rowBase + rmap[s])) * 16u + (uint32_t)tk;
            uint32_t bts = gbits(k0, k1, idx);
            float f = __uint_as_float((bts >> 9) | 0x3f800000u) - 1.0f;
            float u = (f == 0.0f) ? 1.17549435e-38f : f;
            float gu = -logf(-logf(u));
            bsc[s] = pos ? (a_[s] + gu) : NEG_INF;
            bi[s]  = tk;
        }

        // ---- stage 2 (fused): zm + S sums AND argmax, same 4 rounds ----
#pragma unroll
        for (int d = 1; d < 16; d <<= 1) {
#pragma unroll
            for (int s = 0; s < SS; s++) {
                zm[s] += __shfl_xor_sync(0xffffffffu, zm[s], d);
                Sw[s] += __shfl_xor_sync(0xffffffffu, Sw[s], d);
                float os = __shfl_xor_sync(0xffffffffu, bsc[s], d);
                int   oi = __shfl_xor_sync(0xffffffffu, bi[s], d);
                if (os > bsc[s] || (os == bsc[s] && oi < bi[s])) { bsc[s] = os; bi[s] = oi; }
            }
        }

        // ---- finalize: ent = lzm - S/zm ; lp = a_win - lzm ----
        float ent[SS], lp[SS];
#pragma unroll
        for (int s = 0; s < SS; s++) {
            float lzm = logf(zm[s]);
            ent[s] = lzm - Sw[s] / zm[s];
            float a_win = __shfl_sync(0xffffffffu, a_[s], (lane & 16) + bi[s]);
            lp[s] = a_win - lzm;
        }

        // ---- writer lanes: token/state/outputs ----
        if (tk == 0) {
#pragma unroll
            for (int s = 0; s < SS; s++) {
                int r   = rmap[s];
                int tok = bi[s];
                int* st = stw + r * 8;
                int row = rowBase + r;

                seqw[r * 12 + t] = tok;
                int ar  = (tok < 4) ? 2 : ((tok < 8) ? 1 : 0);
                int cnt = st[0] - 1 + ar;
                int ln  = st[1] + 1;
                int act = (cnt > 0) && st[2];
                st[0] = cnt; st[1] = ln; st[2] = act;
                st[3] = st[3] | (tok >= 9);
                st[4] += act;

                out[(size_t)row * 12 + t]                = (float)tok;
                out[OFF_ENT + (size_t)row * 12 + t]      = ent[s];
                out[OFF_LP  + (size_t)row * 12 + t]      = lp[s];
                out[OFF_MASK + (size_t)row * 13 + 1 + t] = act ? 1.0f : 0.0f;
            }
        }
        __syncwarp();

        // ---- parent/sibling scan, parallel across lanes 0..R-1 ----
        if (lane < R) {
            int r = lane;
            int tok = seqw[r * 12 + t];
            int ps0, ps1;
            if (tok < 8) {
                ps0 = tok; ps1 = -1;
            } else {
                ps0 = -1; ps1 = -1;
                int c = 0;
                bool found = false;
                for (int i = t; i >= 0; i--) {
                    int tk2 = seqw[r * 12 + i];
                    int a2 = (tk2 < 4) ? 2 : ((tk2 < 8) ? 1 : 0);
                    c += a2 - 1;
                    if (!found && c == 0) {
                        ps0 = tk2;
                        ps1 = (i + 1 < TSTEPS) ? seqw[r * 12 + i + 1] : -1;
                        found = true;
                    }
                }
            }
            stw[r * 8 + 5] = ps0;
            stw[r * 8 + 6] = ps1;
        }
        __syncwarp();
    }

    // ---- finalize group ----
    if (lane < R) {
        out[OFF_CNT + rowBase + lane] = (float)stw[lane * 8 + 0];
        out[OFF_LEN + rowBase + lane] = (float)stw[lane * 8 + 4];
    }
    __syncwarp();
}

__global__ void __launch_bounds__(THREADS, 2)
eq_sampler(const float* __restrict__ in0, const float* __restrict__ h0,
           const float* __restrict__ Wx, const float* __restrict__ Wh,
           const float* __restrict__ b,  const float* __restrict__ Wp,
           const float* __restrict__ bp, float* __restrict__ out) {
    extern __shared__ float sm[];
    int* smi = (int*)sm;
    const int tid = threadIdx.x;

    for (int i = tid; i < 16384; i += THREADS) sm[SM_WH + i] = Wh[i];
    // transposed, padded Wp: WpT[tok][k], stride 132
    for (int i = tid; i < 2048; i += THREADS) {
        int tok = i >> 7, k = i & 127;
        sm[SM_WPT + tok * 132 + k] = Wp[k * 16 + tok];
    }
    if (tid < 128) sm[SM_B  + tid] = b[tid];
    if (tid < 16)  sm[SM_BP + tid] = bp[tid];
    if (tid < 128) sm[SM_H0 + tid] = h0[tid];

    if (tid == 0) {
        uint32_t* kp = (uint32_t*)(sm + SM_KEY);
#if JAX_PARTITIONABLE
        for (int t = 0; t < TSTEPS; t++) {
            uint32_t a = 0u, bb = (uint32_t)t;
            tf2x32(0u, 42u, a, bb);
            kp[2 * t] = a; kp[2 * t + 1] = bb;
        }
#else
        uint32_t ov[24];
        for (int j = 0; j < 12; j++) {
            uint32_t a = (uint32_t)j, bb = (uint32_t)(j + 12);
            tf2x32(0u, 42u, a, bb);
            ov[j] = a; ov[12 + j] = bb;
        }
        for (int t = 0; t < TSTEPS; t++) { kp[2 * t] = ov[2 * t]; kp[2 * t + 1] = ov[2 * t + 1]; }
#endif
    }
    __syncthreads();

    const int wid  = tid >> 5;
    const int lane = tid & 31;
    const int g    = lane >> 4;
    const int tk   = lane & 15;

    u64t* hw  = (u64t*)(sm + SM_HS) + wid * 512;        // 4 pairs x 128 packed f32x2
    int* seqw = smi + SM_SEQ + wid * 96;                // 8 rows x 12
    int* stw  = smi + SM_ST  + wid * 64;                // 8 rows x 8

    // t=0 input projection (identical for all rows) from global
    float4 xw0v;
    {
        float s0 = 0.f, s1 = 0.f, s2 = 0.f, s3 = 0.f;
#pragma unroll
        for (int k = 0; k < 32; k++) {
            float iv = __ldg(in0 + k);
            const float* wr = Wx + k * 128 + lane * 4;
            s0 = fmaf(iv, __ldg(wr + 0), s0);
            s1 = fmaf(iv, __ldg(wr + 1), s1);
            s2 = fmaf(iv, __ldg(wr + 2), s2);
            s3 = fmaf(iv, __ldg(wr + 3), s3);
        }
        xw0v = make_float4(s0, s1, s2, s3);
    }
    const float4 bvecv = ((const float4*)(sm + SM_B))[lane];
    const float4 hinit = ((const float4*)(sm + SM_H0))[lane];
    const float  bpt   = sm[SM_BP + tk];
    const float4* xwc4 = (const float4*)g_xwc;

    u64t ivd[4];
    ivd[0] = pkdup(xw0v.x + bvecv.x);
    ivd[1] = pkdup(xw0v.y + bvecv.y);
    ivd[2] = pkdup(xw0v.z + bvecv.z);
    ivd[3] = pkdup(xw0v.w + bvecv.w);
    const u64t hi0 = pkdup(hinit.x), hi1 = pkdup(hinit.y);
    const u64t hi2 = pkdup(hinit.z), hi3 = pkdup(hinit.w);

    const int totalWarps = gridDim.x * WPB;
    const int gwid = blockIdx.x * WPB + wid;

    // main phase: R=8 groups, exactly (full8 / totalWarps) per warp
    const int full8 = NROWS / 8;
    const int base8 = (full8 / totalWarps) * totalWarps;
    for (int grp = gwid; grp < base8; grp += totalWarps)
        run_group<8>(grp * 8, sm, hw, seqw, stw, xwc4, out,
                     lane, g, tk, ivd, hi0, hi1, hi2, hi3, bpt);

    // tail phase: remaining rows as R=4 groups
    const int tailRowBase = base8 * 8;
    const int tail4 = (NROWS - tailRowBase) / 4;
    for (int grp = gwid; grp < tail4; grp += totalWarps)
        run_group<4>(tailRowBase + grp * 4, sm, hw, seqw, stw, xwc4, out,
                     lane, g, tk, ivd, hi0, hi1, hi2, hi3, bpt);
}

extern "C" void kernel_launch(void* const* d_in, const int* in_sizes, int n_in,
                              void* d_out, int out_size) {
    int base = (in_sizes[0] == 1) ? 1 : 0;
    const float* in0 = (const float*)d_in[base + 0];
    const float* h0  = (const float*)d_in[base + 1];
    const float* Wx  = (const float*)d_in[base + 2];
    const float* Wh  = (const float*)d_in[base + 3];
    const float* b   = (const float*)d_in[base + 4];
    const float* Wp  = (const float*)d_in[base + 5];
    const float* bp  = (const float*)d_in[base + 6];

    build_xwc<<<289, 128>>>(Wx, b);

    size_t smem = (size_t)SM_TOTF * sizeof(float);
    cudaFuncSetAttribute(eq_sampler, cudaFuncAttributeMaxDynamicSharedMemorySize, (int)smem);
    eq_sampler<<<NBLOCKS, THREADS, smem>>>(in0, h0, Wx, Wh, b, Wp, bp, (float*)d_out);
}

// round 17
// speedup vs baseline: 1.0810x; 1.0024x over previous
#include <cuda_runtime.h>
#include <stdint.h>
#include <math.h>

#define JAX_PARTITIONABLE 1

#define NROWS   65536
#define TSTEPS  12
#define WPB     8
#define THREADS 256
#define NBLOCKS 296        // 2 CTAs/SM on 148 SMs

// output layout (float32): seq | ent | logp | cnt | lengths | mask
#define OFF_ENT  (NROWS * TSTEPS)
#define OFF_LP   (2 * NROWS * TSTEPS)
#define OFF_CNT  (3 * NROWS * TSTEPS)
#define OFF_LEN  (OFF_CNT + NROWS)
#define OFF_MASK (OFF_LEN + NROWS)

// shared layout (float slots)
#define SM_WH    0          // 128x128 = 16384
#define SM_WPT   16384      // 16 x 132 (transposed Wp, padded) = 2112
#define SM_B     18496      // 128
#define SM_BP    18624      // 16
#define SM_H0    18640      // 128
#define SM_KEY   18768      // 24 u32
#define SM_HS    18792      // 8 warps * 4 pairs * 128 f32x2 = 8192 floats (16B aligned)
#define SM_SEQ   26984      // 8 warps * 8 * 12 int = 768
#define SM_ST    27752      // 8 warps * 8 * 8  int = 512
#define SM_TOTF  28264      // 113056 bytes -> 2 CTAs/SM fit

typedef unsigned long long u64t;

// Precomputed x@Wx + b combo table: index (p0+1)*17 + (p1+1), 128 floats each.
__device__ float g_xwc[289 * 128];

__device__ __forceinline__ u64t pk2(float lo, float hi) {
    u64t r;
    asm("mov.b64 %0, {%1, %2};" : "=l"(r) : "f"(lo), "f"(hi));
    return r;
}
__device__ __forceinline__ u64t pkdup(float v) { return pk2(v, v); }
__device__ __forceinline__ void upk2(u64t x, float& lo, float& hi) {
    asm("mov.b64 {%0, %1}, %2;" : "=f"(lo), "=f"(hi) : "l"(x));
}
// packed dual-fp32 FMA (Blackwell): lo/hi halves are independent fp32 FMAs
__device__ __forceinline__ u64t fma2(u64t a, u64t b, u64t c) {
    u64t d;
    asm("fma.rn.f32x2 %0, %1, %2, %3;" : "=l"(d) : "l"(a), "l"(b), "l"(c));
    return d;
}
__device__ __forceinline__ u64t add2(u64t a, u64t b) {
    u64t d;
    asm("add.rn.f32x2 %0, %1, %2;" : "=l"(d) : "l"(a), "l"(b));
    return d;
}

__device__ __forceinline__ uint32_t rotl32(uint32_t x, int n) {
    return (x << n) | (x >> (32 - n));
}

// Threefry-2x32, 20 rounds (exact JAX cipher)
__device__ __forceinline__ void tf2x32(uint32_t k0, uint32_t k1,
                                       uint32_t &x0, uint32_t &x1) {
    uint32_t k2 = k0 ^ k1 ^ 0x1BD11BDAu;
    x0 += k0; x1 += k1;
#define TFR(r) { x0 += x1; x1 = rotl32(x1, (r)); x1 ^= x0; }
    TFR(13) TFR(15) TFR(26) TFR(6)
    x0 += k1; x1 += k2 + 1u;
    TFR(17) TFR(29) TFR(16) TFR(24)
    x0 += k2; x1 += k0 + 2u;
    TFR(13) TFR(15) TFR(26) TFR(6)
    x0 += k0; x1 += k1 + 3u;
    TFR(17) TFR(29) TFR(16) TFR(24)
    x0 += k1; x1 += k2 + 4u;
    TFR(13) TFR(15) TFR(26) TFR(6)
    x0 += k2; x1 += k0 + 5u;
#undef TFR
}

__device__ __forceinline__ uint32_t gbits(uint32_t k0, uint32_t k1, uint32_t idx) {
#if JAX_PARTITIONABLE
    uint32_t a = 0u, b = idx;
    tf2x32(k0, k1, a, b);
    return a ^ b;
#else
    const uint32_t half = (uint32_t)(NROWS * 16) / 2u;
    if (idx < half) {
        uint32_t a = idx, b = idx + half;
        tf2x32(k0, k1, a, b);
        return a;
    } else {
        uint32_t a = idx - half, b = idx;
        tf2x32(k0, k1, a, b);
        return b;
    }
#endif
}

// Prologue: build the (p0,p1) -> xw+b combo table. 289 blocks x 128 threads.
__global__ void build_xwc(const float* __restrict__ Wx, const float* __restrict__ b) {
    int c = blockIdx.x;
    int k = threadIdx.x;
    int i = c / 17, j = c % 17;
    float v = b[k];
    if (i > 0) v += Wx[(i - 1) * 128 + k];
    if (j > 0) v += Wx[(16 + (j - 1)) * 128 + k];
    g_xwc[c * 128 + k] = v;
}

// One group of R rows (R even, R/2 row-pairs). h stored pair-interleaved:
// hw[pair*128 + k] = (h_{2*pair}[k], h_{2*pair+1}[k]) as packed f32x2.
template <int R>
__device__ __forceinline__ void run_group(
    int rowBase, float* __restrict__ sm, u64t* __restrict__ hw,
    int* __restrict__ seqw, int* __restrict__ stw,
    const float4* __restrict__ xwc4, float* __restrict__ out,
    int lane, int g, int tk,
    const u64t* __restrict__ ivd,    // 4: dup(xw0+b) per col (t==0)
    u64t hinit0, u64t hinit1, u64t hinit2, u64t hinit3,
    float bpt)
{
    constexpr int NP = R / 2;     // row pairs
    constexpr int PH = R / 4;     // pairs per half-warp
    constexpr int SS = R / 2;     // scalar sampler streams per half
    const float NEG_INF = __int_as_float(0xff800000);
    const uint32_t* keys = (const uint32_t*)(sm + SM_KEY);

    // stream s -> row r = 2*(g + 2*(s>>1)) + (s&1)  (loop-invariant)
    int rmap[SS];
#pragma unroll
    for (int s = 0; s < SS; s++) rmap[s] = 2 * (g + 2 * (s >> 1)) + (s & 1);

    // ---- init group ----
#pragma unroll
    for (int p = 0; p < NP; p++) {
        u64t* pw = hw + p * 128 + lane * 4;
        pw[0] = hinit0; pw[1] = hinit1; pw[2] = hinit2; pw[3] = hinit3;
    }
    if (lane < R) {
        int* st = stw + lane * 8;
        st[0] = 1; st[1] = 0; st[2] = 1; st[3] = 0; st[4] = 1; st[5] = -1; st[6] = -1;
        out[OFF_MASK + (size_t)(rowBase + lane) * 13] = 1.0f;
    }
    __syncwarp();

    for (int t = 0; t < TSTEPS; t++) {
        const uint32_t k0 = keys[2 * t];
        const uint32_t k1 = keys[2 * t + 1];

        // ---- prefetch xw+b rows (combo table) for this step; consume AFTER matvec ----
        float4 xa[NP], xb[NP];
        if (t > 0) {
#pragma unroll
            for (int p = 0; p < NP; p++) {
                int ia = (stw[(2 * p) * 8 + 5] + 1) * 17 + (stw[(2 * p) * 8 + 6] + 1);
                int ib = (stw[(2 * p + 1) * 8 + 5] + 1) * 17 + (stw[(2 * p + 1) * 8 + 6] + 1);
                xa[p] = __ldg(xwc4 + ia * 32 + lane);
                xb[p] = __ldg(xwc4 + ib * 32 + lane);
            }
        }

        // ---- h @ Wh with packed FFMA2 (acc starts at 0; xw+b added late) ----
        u64t acc2[NP][4];
#pragma unroll
        for (int p = 0; p < NP; p++) {
            acc2[p][0] = 0ull; acc2[p][1] = 0ull; acc2[p][2] = 0ull; acc2[p][3] = 0ull;
        }
        {
            const float4* Wh4 = (const float4*)sm;  // SM_WH == 0
#pragma unroll 1
            for (int k4 = 0; k4 < 32; k4++) {
                u64t hk[NP][4];
#pragma unroll
                for (int p = 0; p < NP; p++) {
                    const u64t* ph = hw + p * 128 + 4 * k4;
                    hk[p][0] = ph[0]; hk[p][1] = ph[1];
                    hk[p][2] = ph[2]; hk[p][3] = ph[3];
                }
#pragma unroll
                for (int kk = 0; kk < 4; kk++) {
                    float4 w = Wh4[(k4 * 4 + kk) * 32 + lane];
                    u64t wd0 = pkdup(w.x), wd1 = pkdup(w.y);
                    u64t wd2 = pkdup(w.z), wd3 = pkdup(w.w);
#pragma unroll
                    for (int p = 0; p < NP; p++) {
                        acc2[p][0] = fma2(hk[p][kk], wd0, acc2[p][0]);
                        acc2[p][1] = fma2(hk[p][kk], wd1, acc2[p][1]);
                        acc2[p][2] = fma2(hk[p][kk], wd2, acc2[p][2]);
                        acc2[p][3] = fma2(hk[p][kk], wd3, acc2[p][3]);
                    }
                }
            }
            __syncwarp();
            // h_new = tanh(acc + (xw + b)) ; store back pair-interleaved
#pragma unroll
            for (int p = 0; p < NP; p++) {
                u64t xw0, xw1, xw2, xw3;
                if (t == 0) {
                    xw0 = ivd[0]; xw1 = ivd[1]; xw2 = ivd[2]; xw3 = ivd[3];
                } else {
                    xw0 = pk2(xa[p].x, xb[p].x);
                    xw1 = pk2(xa[p].y, xb[p].y);
                    xw2 = pk2(xa[p].z, xb[p].z);
                    xw3 = pk2(xa[p].w, xb[p].w);
                }
                u64t s0 = add2(acc2[p][0], xw0);
                u64t s1 = add2(acc2[p][1], xw1);
                u64t s2 = add2(acc2[p][2], xw2);
                u64t s3 = add2(acc2[p][3], xw3);
                u64t* pw = hw + p * 128 + lane * 4;
                float lo, hi;
                upk2(s0, lo, hi); pw[0] = pk2(tanhf(lo), tanhf(hi));
                upk2(s1, lo, hi); pw[1] = pk2(tanhf(lo), tanhf(hi));
                upk2(s2, lo, hi); pw[2] = pk2(tanhf(lo), tanhf(hi));
                upk2(s3, lo, hi); pw[3] = pk2(tanhf(lo), tanhf(hi));
            }
            __syncwarp();
        }

        // ---- logits: lane = token tk; PH pairs for this half ----
        float lg[SS];
        {
            u64t accl2[PH];
#pragma unroll
            for (int q = 0; q < PH; q++) accl2[q] = 0ull;
            const float4* WpT4 = (const float4*)(sm + SM_WPT);
#pragma unroll 4
            for (int k4 = 0; k4 < 32; k4++) {
                float4 wp = WpT4[tk * 33 + k4];
                u64t wd0 = pkdup(wp.x), wd1 = pkdup(wp.y);
                u64t wd2 = pkdup(wp.z), wd3 = pkdup(wp.w);
#pragma unroll
                for (int q = 0; q < PH; q++) {
                    const u64t* ph = hw + (g + 2 * q) * 128 + 4 * k4;
                    ulonglong2 hA = *(const ulonglong2*)(ph);
                    ulonglong2 hB = *(const ulonglong2*)(ph + 2);
                    accl2[q] = fma2(hA.x, wd0, accl2[q]);
                    accl2[q] = fma2(hA.y, wd1, accl2[q]);
                    accl2[q] = fma2(hB.x, wd2, accl2[q]);
                    accl2[q] = fma2(hB.y, wd3, accl2[q]);
                }
            }
#pragma unroll
            for (int q = 0; q < PH; q++) {
                float lo, hi;
                upk2(accl2[q], lo, hi);
                lg[2 * q]     = lo + bpt;
                lg[2 * q + 1] = hi + bpt;
            }
        }

        // ---- constraints (PRE-update state) ----
        bool ok[SS];
#pragma unroll
        for (int s = 0; s < SS; s++) {
            int r = rmap[s];
            int cnt = stw[r * 8 + 0], ln = stw[r * 8 + 1], hv = stw[r * 8 + 3];
            int cl = cnt + ln;
            bool o = true;
            if (tk >= 8 && cl < 2) o = false;
            if (tk <  8 && cl > TSTEPS - 2) o = false;
            if (tk == 8 && cnt == 1 && hv == 0) o = false;
            ok[s] = o;
        }

        // ---- stage 1: max over 16 tokens ----
        float mx[SS];
#pragma unroll
        for (int s = 0; s < SS; s++) mx[s] = lg[s];
#pragma unroll
        for (int d = 1; d < 16; d <<= 1)
#pragma unroll
            for (int s = 0; s < SS; s++)
                mx[s] = fmaxf(mx[s], __shfl_xor_sync(0xffffffffu, mx[s], d));

        // ---- per-lane: ex, masked sums, gumbel score (argmax is lzm-invariant) ----
        float a_[SS], ex[SS], zm[SS], Sw[SS], bsc[SS];
        int bi[SS];
#pragma unroll
        for (int s = 0; s < SS; s++) {
            a_[s] = lg[s] - mx[s];
            ex[s] = expf(a_[s]);
            bool pos = ok[s] && (ex[s] > 0.0f);
            zm[s] = ok[s] ? ex[s] : 0.0f;
            Sw[s] = ok[s] ? ex[s] * a_[s] : 0.0f;
            uint32_t idx = ((uint32_t)(rowBase + rmap[s])) * 16u + (uint32_t)tk;
            uint32_t bts = gbits(k0, k1, idx);
            float f = __uint_as_float((bts >> 9) | 0x3f800000u) - 1.0f;
            float u = (f == 0.0f) ? 1.17549435e-38f : f;
            float gu = -logf(-logf(u));
            bsc[s] = pos ? (a_[s] + gu) : NEG_INF;
            bi[s]  = tk;
        }

        // ---- stage 2 (fused): zm + S sums AND argmax, same 4 rounds ----
#pragma unroll
        for (int d = 1; d < 16; d <<= 1) {
#pragma unroll
            for (int s = 0; s < SS; s++) {
                zm[s] += __shfl_xor_sync(0xffffffffu, zm[s], d);
                Sw[s] += __shfl_xor_sync(0xffffffffu, Sw[s], d);
                float os = __shfl_xor_sync(0xffffffffu, bsc[s], d);
                int   oi = __shfl_xor_sync(0xffffffffu, bi[s], d);
                if (os > bsc[s] || (os == bsc[s] && oi < bi[s])) { bsc[s] = os; bi[s] = oi; }
            }
        }

        // ---- finalize: ent = lzm - S/zm ; lp = a_win - lzm ----
        float ent[SS], lp[SS];
#pragma unroll
        for (int s = 0; s < SS; s++) {
            float lzm = logf(zm[s]);
            ent[s] = lzm - Sw[s] / zm[s];
            float a_win = __shfl_sync(0xffffffffu, a_[s], (lane & 16) + bi[s]);
            lp[s] = a_win - lzm;
        }

        // ---- writer lanes: token/state/outputs ----
        if (tk == 0) {
#pragma unroll
            for (int s = 0; s < SS; s++) {
                int r   = rmap[s];
                int tok = bi[s];
                int* st = stw + r * 8;
                int row = rowBase + r;

                seqw[r * 12 + t] = tok;
                int ar  = (tok < 4) ? 2 : ((tok < 8) ? 1 : 0);
                int cnt = st[0] - 1 + ar;
                int ln  = st[1] + 1;
                int act = (cnt > 0) && st[2];
                st[0] = cnt; st[1] = ln; st[2] = act;
                st[3] = st[3] | (tok >= 9);
                st[4] += act;

                out[(size_t)row * 12 + t]                = (float)tok;
                out[OFF_ENT + (size_t)row * 12 + t]      = ent[s];
                out[OFF_LP  + (size_t)row * 12 + t]      = lp[s];
                out[OFF_MASK + (size_t)row * 13 + 1 + t] = act ? 1.0f : 0.0f;
            }
        }
        __syncwarp();

        // ---- parent/sibling scan, parallel across lanes 0..R-1 ----
        if (lane < R) {
            int r = lane;
            int tok = seqw[r * 12 + t];
            int ps0, ps1;
            if (tok < 8) {
                ps0 = tok; ps1 = -1;
            } else {
                ps0 = -1; ps1 = -1;
                int c = 0;
                bool found = false;
                for (int i = t; i >= 0; i--) {
                    int tk2 = seqw[r * 12 + i];
                    int a2 = (tk2 < 4) ? 2 : ((tk2 < 8) ? 1 : 0);
                    c += a2 - 1;
                    if (!found && c == 0) {
                        ps0 = tk2;
                        ps1 = (i + 1 < TSTEPS) ? seqw[r * 12 + i + 1] : -1;
                        found = true;
                    }
                }
            }
            stw[r * 8 + 5] = ps0;
            stw[r * 8 + 6] = ps1;
        }
        __syncwarp();
    }

    // ---- finalize group ----
    if (lane < R) {
        out[OFF_CNT + rowBase + lane] = (float)stw[lane * 8 + 0];
        out[OFF_LEN + rowBase + lane] = (float)stw[lane * 8 + 4];
    }
    __syncwarp();
}

__global__ void __launch_bounds__(THREADS, 2)
eq_sampler(const float* __restrict__ in0, const float* __restrict__ h0,
           const float* __restrict__ Wx, const float* __restrict__ Wh,
           const float* __restrict__ b,  const float* __restrict__ Wp,
           const float* __restrict__ bp, float* __restrict__ out) {
    extern __shared__ float sm[];
    int* smi = (int*)sm;
    const int tid = threadIdx.x;

    for (int i = tid; i < 16384; i += THREADS) sm[SM_WH + i] = Wh[i];
    // transposed, padded Wp: WpT[tok][k], stride 132
    for (int i = tid; i < 2048; i += THREADS) {
        int tok = i >> 7, k = i & 127;
        sm[SM_WPT + tok * 132 + k] = Wp[k * 16 + tok];
    }
    if (tid < 128) sm[SM_B  + tid] = b[tid];
    if (tid < 16)  sm[SM_BP + tid] = bp[tid];
    if (tid < 128) sm[SM_H0 + tid] = h0[tid];

    if (tid == 0) {
        uint32_t* kp = (uint32_t*)(sm + SM_KEY);
#if JAX_PARTITIONABLE
        for (int t = 0; t < TSTEPS; t++) {
            uint32_t a = 0u, bb = (uint32_t)t;
            tf2x32(0u, 42u, a, bb);
            kp[2 * t] = a; kp[2 * t + 1] = bb;
        }
#else
        uint32_t ov[24];
        for (int j = 0; j < 12; j++) {
            uint32_t a = (uint32_t)j, bb = (uint32_t)(j + 12);
            tf2x32(0u, 42u, a, bb);
            ov[j] = a; ov[12 + j] = bb;
        }
        for (int t = 0; t < TSTEPS; t++) { kp[2 * t] = ov[2 * t]; kp[2 * t + 1] = ov[2 * t + 1]; }
#endif
    }
    __syncthreads();

    const int wid  = tid >> 5;
    const int lane = tid & 31;
    const int g    = lane >> 4;
    const int tk   = lane & 15;

    u64t* hw  = (u64t*)(sm + SM_HS) + wid * 512;        // 4 pairs x 128 packed f32x2
    int* seqw = smi + SM_SEQ + wid * 96;                // 8 rows x 12
    int* stw  = smi + SM_ST  + wid * 64;                // 8 rows x 8

    // t=0 input projection (identical for all rows) from global
    float4 xw0v;
    {
        float s0 = 0.f, s1 = 0.f, s2 = 0.f, s3 = 0.f;
#pragma unroll
        for (int k = 0; k < 32; k++) {
            float iv = __ldg(in0 + k);
            const float* wr = Wx + k * 128 + lane * 4;
            s0 = fmaf(iv, __ldg(wr + 0), s0);
            s1 = fmaf(iv, __ldg(wr + 1), s1);
            s2 = fmaf(iv, __ldg(wr + 2), s2);
            s3 = fmaf(iv, __ldg(wr + 3), s3);
        }
        xw0v = make_float4(s0, s1, s2, s3);
    }
    const float4 bvecv = ((const float4*)(sm + SM_B))[lane];
    const float4 hinit = ((const float4*)(sm + SM_H0))[lane];
    const float  bpt   = sm[SM_BP + tk];
    const float4* xwc4 = (const float4*)g_xwc;

    u64t ivd[4];
    ivd[0] = pkdup(xw0v.x + bvecv.x);
    ivd[1] = pkdup(xw0v.y + bvecv.y);
    ivd[2] = pkdup(xw0v.z + bvecv.z);
    ivd[3] = pkdup(xw0v.w + bvecv.w);
    const u64t hi0 = pkdup(hinit.x), hi1 = pkdup(hinit.y);
    const u64t hi2 = pkdup(hinit.z), hi3 = pkdup(hinit.w);

    const int totalWarps = gridDim.x * WPB;
    const int gwid = blockIdx.x * WPB + wid;

    // main phase: R=8 groups, exactly (full8 / totalWarps) per warp
    const int full8 = NROWS / 8;
    const int base8 = (full8 / totalWarps) * totalWarps;
    for (int grp = gwid; grp < base8; grp += totalWarps)
        run_group<8>(grp * 8, sm, hw, seqw, stw, xwc4, out,
                     lane, g, tk, ivd, hi0, hi1, hi2, hi3, bpt);

    // tail phase: remaining rows as R=4 groups
    const int tailRowBase = base8 * 8;
    const int tail4 = (NROWS - tailRowBase) / 4;
    for (int grp = gwid; grp < tail4; grp += totalWarps)
        run_group<4>(tailRowBase + grp * 4, sm, hw, seqw, stw, xwc4, out,
                     lane, g, tk, ivd, hi0, hi1, hi2, hi3, bpt);
}

extern "C" void kernel_launch(void* const* d_in, const int* in_sizes, int n_in,
                              void* d_out, int out_size) {
    int base = (in_sizes[0] == 1) ? 1 : 0;
    const float* in0 = (const float*)d_in[base + 0];
    const float* h0  = (const float*)d_in[base + 1];
    const float* Wx  = (const float*)d_in[base + 2];
    const float* Wh  = (const float*)d_in[base + 3];
    const float* b   = (const float*)d_in[base + 4];
    const float* Wp  = (const float*)d_in[base + 5];
    const float* bp  = (const float*)d_in[base + 6];

    build_xwc<<<289, 128>>>(Wx, b);

    size_t smem = (size_t)SM_TOTF * sizeof(float);
    cudaFuncSetAttribute(eq_sampler, cudaFuncAttributeMaxDynamicSharedMemorySize, (int)smem);
    eq_sampler<<<NBLOCKS, THREADS, smem>>>(in0, h0, Wx, Wh, b, Wp, bp, (float*)d_out);
}